// round 1
// baseline (speedup 1.0000x reference)
#include <cuda_runtime.h>
#include <math.h>

#define D_IN   128
#define D_OUT  64
#define MAX_N  100000
#define MAX_E  1600000

// ---------------- scratch (static device globals; no allocations) -----------
__device__ float g_H[(size_t)MAX_N * D_OUT];   // 25.6 MB
__device__ float g_ssrc[MAX_N];
__device__ float g_sdst[MAX_N];
__device__ float g_denom[MAX_N];
__device__ float g_ex[MAX_E];                  // 6.4 MB

// ---------------- K0: zero out + denom --------------------------------------
__global__ void k_zero(float* __restrict__ out, int n)
{
    int t = blockIdx.x * blockDim.x + threadIdx.x;
    if (t < n * D_OUT) out[t] = 0.f;
    if (t < n)         g_denom[t] = 0.f;
}

// ---------------- K1: H = X @ W + b  (64 rows/block, 4x4 thread tiles) ------
#define BR 64
__global__ __launch_bounds__(256) void k_gemm(
    const float* __restrict__ X, const float* __restrict__ W,
    const float* __restrict__ b, int n)
{
    __shared__ float Xs[BR][68];        // 64 rows x 64 k-slice, padded
    __shared__ float Ws[64][D_OUT];     // 64 k-slice x 64 cols

    int tid  = threadIdx.x;
    int row0 = blockIdx.x * BR;
    int tr   = tid >> 4;                // 0..15 -> rows tr*4..tr*4+3
    int tc   = tid & 15;                // 0..15 -> cols tc*4..tc*4+3

    float acc[4][4] = {};

    for (int kt = 0; kt < 2; kt++) {    // two K=64 slices of D_IN=128
        // load W slice: 64x64 floats = 16 float4 rows per thread-chunk
        {
            const float4* Wv = (const float4*)(W + (size_t)kt * 64 * D_OUT);
            float4* Wsv = (float4*)Ws;
            #pragma unroll
            for (int i = tid; i < 64 * D_OUT / 4; i += 256)
                Wsv[i] = Wv[i];
        }
        // load X slice: 64 rows x 64 cols
        for (int i = tid; i < BR * 16; i += 256) {
            int r  = i >> 4;
            int c4 = i & 15;
            int gr = row0 + r;
            float4 v = make_float4(0.f, 0.f, 0.f, 0.f);
            if (gr < n)
                v = *(const float4*)(X + (size_t)gr * D_IN + kt * 64 + c4 * 4);
            *(float4*)&Xs[r][c4 * 4] = v;
        }
        __syncthreads();

        #pragma unroll 8
        for (int k = 0; k < 64; k++) {
            float4 wv = *(const float4*)&Ws[k][tc * 4];
            #pragma unroll
            for (int i = 0; i < 4; i++) {
                float x = Xs[tr * 4 + i][k];
                acc[i][0] += x * wv.x;
                acc[i][1] += x * wv.y;
                acc[i][2] += x * wv.z;
                acc[i][3] += x * wv.w;
            }
        }
        __syncthreads();
    }

    float4 bb = *(const float4*)&b[tc * 4];
    #pragma unroll
    for (int i = 0; i < 4; i++) {
        int gr = row0 + tr * 4 + i;
        if (gr < n) {
            float4 o;
            o.x = acc[i][0] + bb.x;
            o.y = acc[i][1] + bb.y;
            o.z = acc[i][2] + bb.z;
            o.w = acc[i][3] + bb.w;
            *(float4*)&g_H[(size_t)gr * D_OUT + tc * 4] = o;
        }
    }
}

// ---------------- K2: per-node scores s_src, s_dst (warp per node) ----------
__global__ void k_scores(const float* __restrict__ a_src,
                         const float* __restrict__ a_dst, int n)
{
    int warp = (blockIdx.x * blockDim.x + threadIdx.x) >> 5;
    int lane = threadIdx.x & 31;
    if (warp >= n) return;
    const float* h = g_H + (size_t)warp * D_OUT;
    float h0 = h[lane], h1 = h[lane + 32];
    float ss = h0 * a_src[lane] + h1 * a_src[lane + 32];
    float sd = h0 * a_dst[lane] + h1 * a_dst[lane + 32];
    #pragma unroll
    for (int off = 16; off; off >>= 1) {
        ss += __shfl_down_sync(0xffffffffu, ss, off);
        sd += __shfl_down_sync(0xffffffffu, sd, off);
    }
    if (lane == 0) { g_ssrc[warp] = ss; g_sdst[warp] = sd; }
}

// ---------------- K3: per-edge exp(elu(score)) + denom accumulation ---------
// Softmax is shift-invariant; scores are bounded (|e| small), so the
// segment-max subtraction in the reference is skipped (mathematically equal).
__global__ void k_edge(const int* __restrict__ esrc,
                       const int* __restrict__ edst, int E)
{
    int t = blockIdx.x * blockDim.x + threadIdx.x;
    if (t >= E) return;
    int d = edst[t];
    float e = g_ssrc[esrc[t]] + g_sdst[d];
    e = e > 0.f ? e : expm1f(e);        // ELU
    float ex = expf(e);
    g_ex[t] = ex;
    atomicAdd(&g_denom[d], ex);
}

// ---------------- K4: scatter-aggregate  out[dst] += H[src] * ex  -----------
// One warp per edge; 2 floats per lane (64 cols). H row is 256B-aligned.
__global__ void k_agg(const int* __restrict__ esrc,
                      const int* __restrict__ edst,
                      float* __restrict__ out, int E)
{
    int warp = (blockIdx.x * blockDim.x + threadIdx.x) >> 5;
    int lane = threadIdx.x & 31;
    if (warp >= E) return;
    int s = esrc[warp];
    int d = edst[warp];
    float w = g_ex[warp];
    float2 h = *(const float2*)(g_H + (size_t)s * D_OUT + lane * 2);
    float* o = out + (size_t)d * D_OUT + lane * 2;
    atomicAdd(o,     h.x * w);
    atomicAdd(o + 1, h.y * w);
}

// ---------------- K5: normalize by denom + final ELU ------------------------
__global__ void k_final(float* __restrict__ out, int n)
{
    int t = blockIdx.x * blockDim.x + threadIdx.x;
    if (t >= n * D_OUT) return;
    float den = g_denom[t >> 6];
    den = den > 0.f ? den : 1.f;
    float v = out[t] / den;
    out[t] = v > 0.f ? v : expm1f(v);
}

// ---------------- launch ----------------------------------------------------
extern "C" void kernel_launch(void* const* d_in, const int* in_sizes, int n_in,
                              void* d_out, int out_size)
{
    const float* X   = (const float*)d_in[0];
    const int*   esr = (const int*)  d_in[1];
    const int*   eds = (const int*)  d_in[2];
    const float* Wt  = (const float*)d_in[3];
    const float* bt  = (const float*)d_in[4];
    const float* asr = (const float*)d_in[5];
    const float* ads = (const float*)d_in[6];
    float* out = (float*)d_out;

    int n = in_sizes[0] / D_IN;
    int E = in_sizes[1];

    k_zero  <<<(n * D_OUT + 255) / 256, 256>>>(out, n);
    k_gemm  <<<(n + BR - 1) / BR, 256>>>(X, Wt, bt, n);
    k_scores<<<(n * 32 + 255) / 256, 256>>>(asr, ads, n);
    k_edge  <<<(E + 255) / 256, 256>>>(esr, eds, E);
    k_agg   <<<(E * 32 + 255) / 256, 256>>>(esr, eds, out, E);
    k_final <<<(n * D_OUT + 255) / 256, 256>>>(out, n);
}

// round 2
// speedup vs baseline: 1.0068x; 1.0068x over previous
#include <cuda_runtime.h>
#include <math.h>

#define D_IN   128
#define D_OUT  64
#define MAX_N  100000
#define MAX_E  1600000

// ---------------- scratch (static device globals; no allocations) -----------
__device__ float g_H[(size_t)MAX_N * D_OUT];   // 25.6 MB
__device__ float g_ssrc[MAX_N];
__device__ float g_sdst[MAX_N];
__device__ float g_denom[MAX_N];
__device__ float g_ex[MAX_E];                  // 6.4 MB

// ---------------- K0: zero out + denom --------------------------------------
__global__ void k_zero(float* __restrict__ out, int n)
{
    int t = blockIdx.x * blockDim.x + threadIdx.x;
    if (t < n * D_OUT) out[t] = 0.f;
    if (t < n)         g_denom[t] = 0.f;
}

// ---------------- K1: H = X @ W + b  (64 rows/block, 4x4 thread tiles) ------
#define BR 64
__global__ __launch_bounds__(256) void k_gemm(
    const float* __restrict__ X, const float* __restrict__ W,
    const float* __restrict__ b, int n)
{
    __shared__ float Xs[BR][68];        // 64 rows x 64 k-slice, padded
    __shared__ float Ws[64][D_OUT];     // 64 k-slice x 64 cols

    int tid  = threadIdx.x;
    int row0 = blockIdx.x * BR;
    int tr   = tid >> 4;                // 0..15 -> rows tr*4..tr*4+3
    int tc   = tid & 15;                // 0..15 -> cols tc*4..tc*4+3

    float acc[4][4] = {};

    for (int kt = 0; kt < 2; kt++) {    // two K=64 slices of D_IN=128
        // load W slice: 64x64 floats = 16 float4 rows per thread-chunk
        {
            const float4* Wv = (const float4*)(W + (size_t)kt * 64 * D_OUT);
            float4* Wsv = (float4*)Ws;
            #pragma unroll
            for (int i = tid; i < 64 * D_OUT / 4; i += 256)
                Wsv[i] = Wv[i];
        }
        // load X slice: 64 rows x 64 cols
        for (int i = tid; i < BR * 16; i += 256) {
            int r  = i >> 4;
            int c4 = i & 15;
            int gr = row0 + r;
            float4 v = make_float4(0.f, 0.f, 0.f, 0.f);
            if (gr < n)
                v = *(const float4*)(X + (size_t)gr * D_IN + kt * 64 + c4 * 4);
            *(float4*)&Xs[r][c4 * 4] = v;
        }
        __syncthreads();

        #pragma unroll 8
        for (int k = 0; k < 64; k++) {
            float4 wv = *(const float4*)&Ws[k][tc * 4];
            #pragma unroll
            for (int i = 0; i < 4; i++) {
                float x = Xs[tr * 4 + i][k];
                acc[i][0] += x * wv.x;
                acc[i][1] += x * wv.y;
                acc[i][2] += x * wv.z;
                acc[i][3] += x * wv.w;
            }
        }
        __syncthreads();
    }

    float4 bb = *(const float4*)&b[tc * 4];
    #pragma unroll
    for (int i = 0; i < 4; i++) {
        int gr = row0 + tr * 4 + i;
        if (gr < n) {
            float4 o;
            o.x = acc[i][0] + bb.x;
            o.y = acc[i][1] + bb.y;
            o.z = acc[i][2] + bb.z;
            o.w = acc[i][3] + bb.w;
            *(float4*)&g_H[(size_t)gr * D_OUT + tc * 4] = o;
        }
    }
}

// ---------------- K2: per-node scores s_src, s_dst (warp per node) ----------
__global__ void k_scores(const float* __restrict__ a_src,
                         const float* __restrict__ a_dst, int n)
{
    int warp = (blockIdx.x * blockDim.x + threadIdx.x) >> 5;
    int lane = threadIdx.x & 31;
    if (warp >= n) return;
    const float* h = g_H + (size_t)warp * D_OUT;
    float h0 = h[lane], h1 = h[lane + 32];
    float ss = h0 * a_src[lane] + h1 * a_src[lane + 32];
    float sd = h0 * a_dst[lane] + h1 * a_dst[lane + 32];
    #pragma unroll
    for (int off = 16; off; off >>= 1) {
        ss += __shfl_down_sync(0xffffffffu, ss, off);
        sd += __shfl_down_sync(0xffffffffu, sd, off);
    }
    if (lane == 0) { g_ssrc[warp] = ss; g_sdst[warp] = sd; }
}

// ---------------- K3: per-edge exp(elu(score)) + denom accumulation ---------
// Softmax is shift-invariant; scores are bounded (|e| small), so the
// segment-max subtraction in the reference is skipped (mathematically equal).
__global__ void k_edge(const int* __restrict__ esrc,
                       const int* __restrict__ edst, int E)
{
    int t = blockIdx.x * blockDim.x + threadIdx.x;
    if (t >= E) return;
    int d = edst[t];
    float e = g_ssrc[esrc[t]] + g_sdst[d];
    e = e > 0.f ? e : expm1f(e);        // ELU
    float ex = expf(e);
    g_ex[t] = ex;
    atomicAdd(&g_denom[d], ex);
}

// ---------------- K4: scatter-aggregate  out[dst] += H[src] * ex  -----------
// One warp per edge; 2 floats per lane (64 cols). H row is 256B-aligned.
__global__ void k_agg(const int* __restrict__ esrc,
                      const int* __restrict__ edst,
                      float* __restrict__ out, int E)
{
    int warp = (blockIdx.x * blockDim.x + threadIdx.x) >> 5;
    int lane = threadIdx.x & 31;
    if (warp >= E) return;
    int s = esrc[warp];
    int d = edst[warp];
    float w = g_ex[warp];
    float2 h = *(const float2*)(g_H + (size_t)s * D_OUT + lane * 2);
    float* o = out + (size_t)d * D_OUT + lane * 2;
    atomicAdd(o,     h.x * w);
    atomicAdd(o + 1, h.y * w);
}

// ---------------- K5: normalize by denom + final ELU ------------------------
__global__ void k_final(float* __restrict__ out, int n)
{
    int t = blockIdx.x * blockDim.x + threadIdx.x;
    if (t >= n * D_OUT) return;
    float den = g_denom[t >> 6];
    den = den > 0.f ? den : 1.f;
    float v = out[t] / den;
    out[t] = v > 0.f ? v : expm1f(v);
}

// ---------------- launch ----------------------------------------------------
extern "C" void kernel_launch(void* const* d_in, const int* in_sizes, int n_in,
                              void* d_out, int out_size)
{
    const float* X   = (const float*)d_in[0];
    const int*   esr = (const int*)  d_in[1];
    const int*   eds = (const int*)  d_in[2];
    const float* Wt  = (const float*)d_in[3];
    const float* bt  = (const float*)d_in[4];
    const float* asr = (const float*)d_in[5];
    const float* ads = (const float*)d_in[6];
    float* out = (float*)d_out;

    int n = in_sizes[0] / D_IN;
    int E = in_sizes[1];

    k_zero  <<<(n * D_OUT + 255) / 256, 256>>>(out, n);
    k_gemm  <<<(n + BR - 1) / BR, 256>>>(X, Wt, bt, n);
    k_scores<<<(n * 32 + 255) / 256, 256>>>(asr, ads, n);
    k_edge  <<<(E + 255) / 256, 256>>>(esr, eds, E);
    k_agg   <<<(E * 32 + 255) / 256, 256>>>(esr, eds, out, E);
    k_final <<<(n * D_OUT + 255) / 256, 256>>>(out, n);
}